// round 2
// baseline (speedup 1.0000x reference)
#include <cuda_runtime.h>
#include <cstdint>

#define N_NODES 100000
#define IN_DIM  128
#define EMB     64
#define NCLS    18
#define MAX_E   3200000

// ---------------- scratch (static device globals; no allocs) ----------------
__device__ float g_deg[N_NODES];
__device__ float g_dis[N_NODES];
__device__ float g_h1 [N_NODES * EMB];
__device__ float g_agg1[N_NODES * EMB];
__device__ float g_h2 [N_NODES * NCLS];
__device__ float g_agg2[N_NODES * NCLS];
__device__ int   g_src[MAX_E];
__device__ int   g_dst[MAX_E];
__device__ float g_nrm[MAX_E];

// ---------------- vector RED helpers (no-return global atomics) -------------
__device__ __forceinline__ void red_add_v4(float* p, float4 v) {
    asm volatile("red.global.add.v4.f32 [%0], {%1,%2,%3,%4};"
                 :: "l"(__cvta_generic_to_global(p)),
                    "f"(v.x), "f"(v.y), "f"(v.z), "f"(v.w) : "memory");
}
__device__ __forceinline__ void red_add_v2(float* p, float2 v) {
    asm volatile("red.global.add.v2.f32 [%0], {%1,%2};"
                 :: "l"(__cvta_generic_to_global(p)),
                    "f"(v.x), "f"(v.y) : "memory");
}

// ---------------- kernels ---------------------------------------------------

// deg[i] = 1 (self loop)
__global__ void k_deg_init() {
    int i = blockIdx.x * blockDim.x + threadIdx.x;
    if (i < N_NODES) g_deg[i] = 1.0f;
}

// deg[dst] += 1 for each edge   (edge_index is int32 per harness dtype rules)
__global__ void k_deg(const int* __restrict__ ei, int E) {
    int e = blockIdx.x * blockDim.x + threadIdx.x;
    if (e < E) {
        int d = ei[E + e];
        if ((unsigned)d < N_NODES) atomicAdd(&g_deg[d], 1.0f);
    }
}

// dis = rsqrt(deg)   (deg >= 1 always due to self loops)
__global__ void k_dis() {
    int i = blockIdx.x * blockDim.x + threadIdx.x;
    if (i < N_NODES) g_dis[i] = rsqrtf(g_deg[i]);
}

// int32 src/dst + per-edge norm
__global__ void k_prep(const int* __restrict__ ei, int E) {
    int e = blockIdx.x * blockDim.x + threadIdx.x;
    if (e < E) {
        int s = ei[e];
        int d = ei[E + e];
        if ((unsigned)s >= N_NODES) s = 0;
        if ((unsigned)d >= N_NODES) d = 0;
        g_src[e] = s;
        g_dst[e] = d;
        g_nrm[e] = g_dis[s] * g_dis[d];
    }
}

// h1 = x @ W1   (100000x128 @ 128x64), W1 staged in smem, 64 rows per block
#define G1_ROWS 64
__global__ void k_gemm1(const float* __restrict__ x, const float* __restrict__ W1) {
    __shared__ float sW[IN_DIM * EMB];  // 32 KB
    for (int i = threadIdx.x; i < IN_DIM * EMB; i += blockDim.x) sW[i] = W1[i];
    __syncthreads();
    int col = threadIdx.x;  // 0..63
    int row0 = blockIdx.x * G1_ROWS;
    int row1 = min(row0 + G1_ROWS, N_NODES);
    for (int row = row0; row < row1; ++row) {
        const float4* x4 = (const float4*)(x + (size_t)row * IN_DIM);
        float acc = 0.f;
#pragma unroll
        for (int k4 = 0; k4 < IN_DIM / 4; ++k4) {
            float4 xv = x4[k4];
            int k = k4 * 4;
            acc += xv.x * sW[(k + 0) * EMB + col];
            acc += xv.y * sW[(k + 1) * EMB + col];
            acc += xv.z * sW[(k + 2) * EMB + col];
            acc += xv.w * sW[(k + 3) * EMB + col];
        }
        g_h1[(size_t)row * EMB + col] = acc;
    }
}

// agg1 init with self-loop contribution: agg1[i,:] = h1[i,:] * dis[i]^2
__global__ void k_self1() {
    int i = blockIdx.x * blockDim.x + threadIdx.x;
    if (i < N_NODES * EMB) {
        float di = g_dis[i >> 6];  // /EMB
        g_agg1[i] = g_h1[i] * di * di;
    }
}

// edge scatter layer 1: warp handles 2 edges; 16 lanes x float4 = 64 floats/edge
__global__ void k_edge1(int E) {
    int warp = (blockIdx.x * blockDim.x + threadIdx.x) >> 5;
    int lane = threadIdx.x & 31;
    int e = warp * 2 + (lane >> 4);
    if (e >= E) return;
    int j = lane & 15;
    int s = g_src[e];
    int d = g_dst[e];
    float nrm = g_nrm[e];
    float4 v = *(const float4*)&g_h1[(size_t)s * EMB + j * 4];
    v.x *= nrm; v.y *= nrm; v.z *= nrm; v.w *= nrm;
    red_add_v4(&g_agg1[(size_t)d * EMB + j * 4], v);
}

// fused: r = relu(agg1 + b1); h2 = r @ W2; agg2 init = h2 * dis^2
// block: 16 nodes x 18 classes
__global__ void k_layer2(const float* __restrict__ b1, const float* __restrict__ W2) {
    __shared__ float sA[16 * EMB];       // relu'd activations
    __shared__ float sW[EMB * NCLS];     // W2
    int t = threadIdx.y * NCLS + threadIdx.x;  // 0..287
    int node0 = blockIdx.x * 16;
    for (int idx = t; idx < 16 * EMB; idx += 16 * NCLS) {
        int r = idx >> 6, c = idx & 63;
        int node = node0 + r;
        float v = 0.f;
        if (node < N_NODES) v = fmaxf(g_agg1[(size_t)node * EMB + c] + b1[c], 0.f);
        sA[idx] = v;
    }
    for (int idx = t; idx < EMB * NCLS; idx += 16 * NCLS) sW[idx] = W2[idx];
    __syncthreads();
    int c = threadIdx.x;        // 0..17
    int nl = threadIdx.y;       // 0..15
    int node = node0 + nl;
    if (node >= N_NODES) return;
    float acc = 0.f;
#pragma unroll
    for (int k = 0; k < EMB; ++k) acc += sA[nl * EMB + k] * sW[k * NCLS + c];
    float di = g_dis[node];
    g_h2 [(size_t)node * NCLS + c] = acc;
    g_agg2[(size_t)node * NCLS + c] = acc * di * di;
}

// edge scatter layer 2: warp handles 2 edges; lanes j<9 x float2 = 18 floats/edge
__global__ void k_edge2(int E) {
    int warp = (blockIdx.x * blockDim.x + threadIdx.x) >> 5;
    int lane = threadIdx.x & 31;
    int e = warp * 2 + (lane >> 4);
    if (e >= E) return;
    int j = lane & 15;
    if (j >= 9) return;
    int s = g_src[e];
    int d = g_dst[e];
    float nrm = g_nrm[e];
    float2 v = *(const float2*)&g_h2[(size_t)s * NCLS + j * 2];
    v.x *= nrm; v.y *= nrm;
    red_add_v2(&g_agg2[(size_t)d * NCLS + j * 2], v);
}

// logits = agg2 + b2 ; out[0:N*18) = log_softmax(logits) ; out[N*18:2*N*18) = logits
__global__ void k_final(const float* __restrict__ b2, float* __restrict__ out,
                        int write_logits) {
    int n = blockIdx.x * blockDim.x + threadIdx.x;
    if (n >= N_NODES) return;
    float v[NCLS];
    float m = -1e30f;
#pragma unroll
    for (int c = 0; c < NCLS; ++c) {
        v[c] = g_agg2[(size_t)n * NCLS + c] + b2[c];
        m = fmaxf(m, v[c]);
    }
    float s = 0.f;
#pragma unroll
    for (int c = 0; c < NCLS; ++c) s += __expf(v[c] - m);
    float lse = m + __logf(s);
#pragma unroll
    for (int c = 0; c < NCLS; ++c) out[(size_t)n * NCLS + c] = v[c] - lse;
    if (write_logits) {
#pragma unroll
        for (int c = 0; c < NCLS; ++c)
            out[(size_t)N_NODES * NCLS + (size_t)n * NCLS + c] = v[c];
    }
}

// ---------------- launch -----------------------------------------------------
extern "C" void kernel_launch(void* const* d_in, const int* in_sizes, int n_in,
                              void* d_out, int out_size) {
    const float* x  = (const float*)d_in[0];
    const int*   ei = (const int*)d_in[1];     // int64 downcast to int32 by harness
    const float* W1 = (const float*)d_in[2];
    const float* b1 = (const float*)d_in[3];
    const float* W2 = (const float*)d_in[4];
    const float* b2 = (const float*)d_in[5];
    float* out = (float*)d_out;

    int E = in_sizes[1] / 2;
    if (E > MAX_E) E = MAX_E;

    int write_logits = (out_size >= 2 * N_NODES * NCLS) ? 1 : 0;

    k_deg_init<<<(N_NODES + 255) / 256, 256>>>();
    k_deg<<<(E + 255) / 256, 256>>>(ei, E);
    k_dis<<<(N_NODES + 255) / 256, 256>>>();
    k_prep<<<(E + 255) / 256, 256>>>(ei, E);

    k_gemm1<<<(N_NODES + G1_ROWS - 1) / G1_ROWS, EMB>>>(x, W1);
    k_self1<<<(N_NODES * EMB + 255) / 256, 256>>>();
    k_edge1<<<(E + 15) / 16, 256>>>(E);   // 8 warps/block * 2 edges/warp

    k_layer2<<<(N_NODES + 15) / 16, dim3(NCLS, 16)>>>(b1, W2);
    k_edge2<<<(E + 15) / 16, 256>>>(E);

    k_final<<<(N_NODES + 127) / 128, 128>>>(b2, out, write_logits);
}